// round 10
// baseline (speedup 1.0000x reference)
#include <cuda_runtime.h>
#include <cstdint>

// FinePreprocess: gather 5x5 windows (stride 4, pad 2) from two NCHW f32
// feature maps at per-match window indices. Output = concat[(M,25,C) f0,
// (M,25,C) f1]; per-match flat layout is c*25 + wy*5 + wx.
//
// R10: counting-sort patches by (f,b,idx) so duplicate / spatially adjacent
// windows are processed by consecutive blocks -> their gathered 64B DRAM
// blocks hit in L2 instead of re-fetching. Main gather kernel = R8 structure
// (fastest so far), reading its patch id through the sorted permutation.

#define FP_N 4
#define FP_C 128
#define FP_H 240
#define FP_W 320
#define FP_OUTW 80
#define FP_L 4800            // 60*80
#define PATCH_VEC4 800
#define PATCH_WORDS 3200
#define NKEYS (2 * FP_N * FP_L)   // 38400 (feature, batch, window)

#define SCAN_T 1024
#define SCAN_PER ((NKEYS + SCAN_T - 1) / SCAN_T)   // 38

__device__ int g_hist[NKEYS];
__device__ int g_order[24000];

__device__ __forceinline__ int patch_key(int p, int M,
                                         const int* __restrict__ b_ids,
                                         const int* __restrict__ i_ids,
                                         const int* __restrict__ j_ids)
{
    int f = p >= M;
    int m = f ? p - M : p;
    int b   = min(max(b_ids[m], 0), FP_N - 1);
    int idx = min(max((f ? j_ids : i_ids)[m], 0), FP_L - 1);
    return (f * FP_N + b) * FP_L + idx;
}

__global__ void zero_hist_kernel()
{
    int i = blockIdx.x * blockDim.x + threadIdx.x;
    if (i < NKEYS) g_hist[i] = 0;
}

__global__ void hist_kernel(const int* __restrict__ b_ids,
                            const int* __restrict__ i_ids,
                            const int* __restrict__ j_ids, int M)
{
    int p = blockIdx.x * blockDim.x + threadIdx.x;
    if (p >= 2 * M) return;
    atomicAdd(&g_hist[patch_key(p, M, b_ids, i_ids, j_ids)], 1);
}

// Single-block exclusive scan over the 38400-bin histogram (in place).
__global__ void __launch_bounds__(SCAN_T)
scan_kernel()
{
    __shared__ int partial[SCAN_T];
    int t = threadIdx.x;
    int base = t * SCAN_PER;

    int s = 0;
    for (int i = 0; i < SCAN_PER; i++) {
        int k = base + i;
        if (k < NKEYS) s += g_hist[k];
    }
    partial[t] = s;
    __syncthreads();

    // Hillis-Steele inclusive scan
    for (int off = 1; off < SCAN_T; off <<= 1) {
        int v = (t >= off) ? partial[t - off] : 0;
        __syncthreads();
        partial[t] += v;
        __syncthreads();
    }
    int run = partial[t] - s;   // exclusive prefix of this chunk

    for (int i = 0; i < SCAN_PER; i++) {
        int k = base + i;
        if (k < NKEYS) {
            int v = g_hist[k];
            g_hist[k] = run;
            run += v;
        }
    }
}

__global__ void scatter_kernel(const int* __restrict__ b_ids,
                               const int* __restrict__ i_ids,
                               const int* __restrict__ j_ids, int M)
{
    int p = blockIdx.x * blockDim.x + threadIdx.x;
    if (p >= 2 * M) return;
    int key = patch_key(p, M, b_ids, i_ids, j_ids);
    int pos = atomicAdd(&g_hist[key], 1);
    g_order[pos] = p;
}

// Main gather: one block per patch, taken in sorted order.
__global__ void __launch_bounds__(640, 3)
fine_gather_kernel(const float* __restrict__ feat0,
                   const float* __restrict__ feat1,
                   const int* __restrict__ b_ids,
                   const int* __restrict__ i_ids,
                   const int* __restrict__ j_ids,
                   float* __restrict__ out,
                   int M)
{
    __shared__ float s[PATCH_WORDS];

    int p   = g_order[blockIdx.x];
    int f   = p >= M;
    int m   = f ? p - M : p;
    int tid = threadIdx.x;           // 0..639 == c*5 + wy

    int b   = min(max(b_ids[m], 0), FP_N - 1);
    int idx = min(max((f ? j_ids : i_ids)[m], 0), FP_L - 1);
    int gy  = idx / FP_OUTW;
    int gx  = idx - gy * FP_OUTW;

    int c  = tid / 5;
    int wy = tid - 5 * c;
    int h  = gy * 4 + wy - 2;

    const float* __restrict__ src = f ? feat1 : feat0;

    float4 A = make_float4(0.f, 0.f, 0.f, 0.f);
    float4 B = make_float4(0.f, 0.f, 0.f, 0.f);
    if (h >= 0 && h < FP_H) {
        const float4* __restrict__ row4 = (const float4*)
            (src + (((long long)b * FP_C + c) * FP_H + h) * FP_W);
        if (gx > 0)                      // block-uniform branch
            A = __ldg(row4 + (gx - 1));  // elements 4gx-4 .. 4gx-1
        B = __ldg(row4 + gx);            // elements 4gx   .. 4gx+3
    }
    // window = elements 4gx-2 .. 4gx+2 -> {A.z, A.w, B.x, B.y, B.z}
    float* __restrict__ srow = s + tid * 5;   // word 5*(c*5+wy) = c*25+wy*5
    srow[0] = A.z;
    srow[1] = A.w;
    srow[2] = B.x;
    srow[3] = B.y;
    srow[4] = B.z;

    __syncthreads();

    // coalesced full-sector writeout, 800 float4 per patch
    float4* __restrict__ out4 = (float4*)out + (long long)p * PATCH_VEC4;
    const float4* __restrict__ s4 = (const float4*)s;
    out4[tid] = s4[tid];
    if (tid < PATCH_VEC4 - 640)
        out4[640 + tid] = s4[640 + tid];
}

extern "C" void kernel_launch(void* const* d_in, const int* in_sizes, int n_in,
                              void* d_out, int out_size)
{
    // metadata order: feat_f0, feat_f1, hw0_f, hw0_c, b_ids, i_ids, j_ids
    const float* feat0 = (const float*)d_in[0];
    const float* feat1 = (const float*)d_in[1];
    const int*   b_ids = (const int*)d_in[4];
    const int*   i_ids = (const int*)d_in[5];
    const int*   j_ids = (const int*)d_in[6];
    float* out = (float*)d_out;

    int M = in_sizes[4];   // 6000
    int P = 2 * M;

    zero_hist_kernel<<<(NKEYS + 255) / 256, 256>>>();
    hist_kernel<<<(P + 255) / 256, 256>>>(b_ids, i_ids, j_ids, M);
    scan_kernel<<<1, SCAN_T>>>();
    scatter_kernel<<<(P + 255) / 256, 256>>>(b_ids, i_ids, j_ids, M);
    fine_gather_kernel<<<P, 640>>>(feat0, feat1, b_ids, i_ids, j_ids, out, M);
}

// round 11
// speedup vs baseline: 1.1309x; 1.1309x over previous
#include <cuda_runtime.h>
#include <cstdint>

// FinePreprocess: gather 5x5 windows (stride 4, pad 2) from two NCHW f32
// feature maps at per-match window indices. Output = concat[(M,25,C) f0,
// (M,25,C) f1]; per-match flat layout is c*25 + wy*5 + wx.
//
// R11 = R8 structure (best: 127us) + streaming cache hints:
//   - feature gathers via ld.global.cs (stream-once, evict-first)
//   - output writeout via st.global.cs (write-once, never read)
// One block per (feature, match) patch:
//  Phase 1: 640 threads, one (c,wy) row each. w0 = 4*gx-2 ≡ 2 mod 4, so the
//           5-float window is exactly two aligned float4 blocks (4(gx-1), 4gx)
//           with fixed extraction {A.z,A.w,B.x,B.y,B.z}; sector-minimal.
//  Phase 2: patch staged in smem in output order, written as 800 float4
//           fully coalesced (full-sector STG.128).

#define FP_N 4
#define FP_C 128
#define FP_H 240
#define FP_W 320
#define FP_OUTW 80
#define FP_L 4800           // 60*80
#define PATCH_WORDS 3200    // C*25
#define PATCH_VEC4 800

__device__ __forceinline__ float4 ldcs4(const float4* p)
{
    float4 v;
    asm volatile("ld.global.cs.v4.f32 {%0,%1,%2,%3}, [%4];"
                 : "=f"(v.x), "=f"(v.y), "=f"(v.z), "=f"(v.w)
                 : "l"(p));
    return v;
}

__device__ __forceinline__ void stcs4(float4* p, float4 v)
{
    asm volatile("st.global.cs.v4.f32 [%0], {%1,%2,%3,%4};"
                 :: "l"(p), "f"(v.x), "f"(v.y), "f"(v.z), "f"(v.w)
                 : "memory");
}

__global__ void __launch_bounds__(640, 3)
fine_gather_kernel(const float* __restrict__ feat0,
                   const float* __restrict__ feat1,
                   const int* __restrict__ b_ids,
                   const int* __restrict__ i_ids,
                   const int* __restrict__ j_ids,
                   float* __restrict__ out,
                   int M)
{
    __shared__ float s[PATCH_WORDS];

    int blk = blockIdx.x;            // [0, 2M): feat0 patches then feat1 patches
    int f   = blk >= M;
    int m   = f ? blk - M : blk;
    int tid = threadIdx.x;           // 0..639 == c*5 + wy

    // block-uniform scalars (L1 broadcast). Clamp = no-op on valid data.
    int b   = min(max(b_ids[m], 0), FP_N - 1);
    int idx = min(max((f ? j_ids : i_ids)[m], 0), FP_L - 1);
    int gy  = idx / FP_OUTW;
    int gx  = idx - gy * FP_OUTW;

    int c  = tid / 5;
    int wy = tid - 5 * c;
    int h  = gy * 4 + wy - 2;

    const float* __restrict__ src = f ? feat1 : feat0;

    float4 A = make_float4(0.f, 0.f, 0.f, 0.f);
    float4 B = make_float4(0.f, 0.f, 0.f, 0.f);
    if (h >= 0 && h < FP_H) {
        const float4* __restrict__ row4 = (const float4*)
            (src + (((long long)b * FP_C + c) * FP_H + h) * FP_W);
        if (gx > 0)                      // block-uniform branch
            A = ldcs4(row4 + (gx - 1));  // elements 4gx-4 .. 4gx-1
        B = ldcs4(row4 + gx);            // elements 4gx   .. 4gx+3
    }
    // window = elements 4gx-2 .. 4gx+2  ->  {A.z, A.w, B.x, B.y, B.z}
    float* __restrict__ srow = s + tid * 5;   // word 5*(c*5+wy) = c*25+wy*5
    srow[0] = A.z;
    srow[1] = A.w;
    srow[2] = B.x;
    srow[3] = B.y;
    srow[4] = B.z;

    __syncthreads();

    // Phase 2: coalesced full-sector streaming writeout, 800 float4 per patch.
    float4* __restrict__ out4 = (float4*)out + (long long)blk * PATCH_VEC4;
    const float4* __restrict__ s4 = (const float4*)s;
    stcs4(out4 + tid, s4[tid]);
    if (tid < PATCH_VEC4 - 640)
        stcs4(out4 + 640 + tid, s4[640 + tid]);
}

extern "C" void kernel_launch(void* const* d_in, const int* in_sizes, int n_in,
                              void* d_out, int out_size)
{
    // metadata order: feat_f0, feat_f1, hw0_f, hw0_c, b_ids, i_ids, j_ids
    const float* feat0 = (const float*)d_in[0];
    const float* feat1 = (const float*)d_in[1];
    const int*   b_ids = (const int*)d_in[4];
    const int*   i_ids = (const int*)d_in[5];
    const int*   j_ids = (const int*)d_in[6];
    float* out = (float*)d_out;

    int M = in_sizes[4];   // 6000

    fine_gather_kernel<<<2 * M, 640>>>(feat0, feat1, b_ids, i_ids, j_ids, out, M);
}

// round 14
// speedup vs baseline: 1.1857x; 1.0484x over previous
#include <cuda_runtime.h>
#include <cstdint>

// FinePreprocess: gather 5x5 windows (stride 4, pad 2) from two NCHW f32
// feature maps at per-match window indices. Output = concat[(M,25,C) f0,
// (M,25,C) f1]; per-match flat layout is c*25 + wy*5 + wx.
//
// R12 (resubmitted after infra failure): 2 adjacent patches per block, flat:
//   - all 4 gather LDG.128s issued before the single barrier (MLP 2->4),
//   - patches 2k,2k+1 are adjacent in the output, so both smem buffers form
//     one contiguous 1600-float4 span -> fused fully-coalesced writeout,
//   - half the barriers of R8.

#define FP_N 4
#define FP_C 128
#define FP_H 240
#define FP_W 320
#define FP_OUTW 80
#define FP_L 4800            // 60*80
#define PATCH_WORDS 3200     // C*25
#define BLOCK_VEC4 1600      // 2 patches * 800 float4

__device__ __forceinline__ void stcs4(float4* p, float4 v)
{
    asm volatile("st.global.cs.v4.f32 [%0], {%1,%2,%3,%4};"
                 :: "l"(p), "f"(v.x), "f"(v.y), "f"(v.z), "f"(v.w)
                 : "memory");
}

__device__ __forceinline__ void gather_row(
    int p, int M, int wy, int c,
    const float* __restrict__ feat0, const float* __restrict__ feat1,
    const int* __restrict__ b_ids, const int* __restrict__ i_ids,
    const int* __restrict__ j_ids,
    float4& A, float4& B)
{
    int f = p >= M;
    int m = f ? p - M : p;

    int b   = min(max(b_ids[m], 0), FP_N - 1);        // block-uniform, L1 bcast
    int idx = min(max((f ? j_ids : i_ids)[m], 0), FP_L - 1);
    int gy  = idx / FP_OUTW;
    int gx  = idx - gy * FP_OUTW;
    int h   = gy * 4 + wy - 2;

    A = make_float4(0.f, 0.f, 0.f, 0.f);
    B = make_float4(0.f, 0.f, 0.f, 0.f);
    if (h >= 0 && h < FP_H) {
        const float* __restrict__ src = f ? feat1 : feat0;
        const float4* __restrict__ row4 = (const float4*)
            (src + (((long long)b * FP_C + c) * FP_H + h) * FP_W);
        if (gx > 0)                      // block-uniform branch
            A = __ldg(row4 + (gx - 1));  // elements 4gx-4 .. 4gx-1
        B = __ldg(row4 + gx);            // elements 4gx   .. 4gx+3
    }
    // window = elements 4gx-2 .. 4gx+2  ->  {A.z, A.w, B.x, B.y, B.z}
}

__global__ void __launch_bounds__(640, 3)
fine_gather_kernel(const float* __restrict__ feat0,
                   const float* __restrict__ feat1,
                   const int* __restrict__ b_ids,
                   const int* __restrict__ i_ids,
                   const int* __restrict__ j_ids,
                   float* __restrict__ out,
                   int M)
{
    __shared__ float s[2 * PATCH_WORDS];   // patches 2k and 2k+1, output order

    int tid = threadIdx.x;            // 0..639 == c*5 + wy
    int c   = tid / 5;
    int wy  = tid - 5 * c;
    int p0  = blockIdx.x * 2;         // 2M is always even -> p0+1 valid

    // issue all gathers up front: 4 independent LDG.128 in flight per thread
    float4 A0, B0, A1, B1;
    gather_row(p0,     M, wy, c, feat0, feat1, b_ids, i_ids, j_ids, A0, B0);
    gather_row(p0 + 1, M, wy, c, feat0, feat1, b_ids, i_ids, j_ids, A1, B1);

    float* __restrict__ s0 = s + tid * 5;                 // patch p0 row
    float* __restrict__ s1 = s + PATCH_WORDS + tid * 5;   // patch p0+1 row
    s0[0] = A0.z; s0[1] = A0.w; s0[2] = B0.x; s0[3] = B0.y; s0[4] = B0.z;
    s1[0] = A1.z; s1[1] = A1.w; s1[2] = B1.x; s1[3] = B1.y; s1[4] = B1.z;

    __syncthreads();

    // fused writeout: 1600 consecutive float4 covering both patches
    float4* __restrict__ out4 = (float4*)out + (long long)p0 * 800;
    const float4* __restrict__ s4 = (const float4*)s;
    stcs4(out4 + tid,        s4[tid]);
    stcs4(out4 + 640 + tid,  s4[640 + tid]);
    if (tid < BLOCK_VEC4 - 1280)
        stcs4(out4 + 1280 + tid, s4[1280 + tid]);
}

extern "C" void kernel_launch(void* const* d_in, const int* in_sizes, int n_in,
                              void* d_out, int out_size)
{
    // metadata order: feat_f0, feat_f1, hw0_f, hw0_c, b_ids, i_ids, j_ids
    const float* feat0 = (const float*)d_in[0];
    const float* feat1 = (const float*)d_in[1];
    const int*   b_ids = (const int*)d_in[4];
    const int*   i_ids = (const int*)d_in[5];
    const int*   j_ids = (const int*)d_in[6];
    float* out = (float*)d_out;

    int M = in_sizes[4];   // 6000

    fine_gather_kernel<<<M, 640>>>(feat0, feat1, b_ids, i_ids, j_ids, out, M);
}